// round 17
// baseline (speedup 1.0000x reference)
#include <cuda_runtime.h>

#define CC 192
#define HW4 2304u     // H*W/4 = float4-groups per channel
#define PSTRIDE 59    // 33 softplus(mat) + 13 bias + 13 tanh(factor)

__device__ __forceinline__ float fast_sigmoid(float x) {
    float e = __expf(-x);
    return __fdividef(1.0f, 1.0f + e);
}

__device__ __forceinline__ float fast_tanh(float x) {
    float y;
    asm("tanh.approx.f32 %0, %1;" : "=f"(y) : "f"(x));
    return y;
}

__device__ __forceinline__ float softplus_fast(float x) {
    return (x > 15.0f) ? x : __logf(1.0f + __expf(x));
}

// Transformed value of parameter slot s (0..58) for channel c.
__device__ __forceinline__ float load_slot(int s, unsigned c,
    const float* m0, const float* m1, const float* m2,
    const float* m3, const float* m4,
    const float* b0, const float* b1, const float* b2,
    const float* b3, const float* b4,
    const float* f0, const float* f1, const float* f2,
    const float* f3, const float* f4)
{
    if (s < 33) {
        const float* ms[5] = {m0, m1, m2, m3, m4};
        const int moff[5] = {0, 3, 12, 21, 30};
        const int msz[5]  = {3, 9, 9, 9, 3};
        int l = (s < 3) ? 0 : (s < 12) ? 1 : (s < 21) ? 2 : (s < 30) ? 3 : 4;
        return softplus_fast(ms[l][c * msz[l] + (s - moff[l])]);
    } else if (s < 46) {
        const float* bs[5] = {b0, b1, b2, b3, b4};
        const int uoff[5] = {0, 3, 6, 9, 12};
        const int usz[5]  = {3, 3, 3, 3, 1};
        int u = s - 33;
        int l = (u < 3) ? 0 : (u < 6) ? 1 : (u < 9) ? 2 : (u < 12) ? 3 : 4;
        return bs[l][c * usz[l] + (u - uoff[l])];
    } else {
        const float* fs[5] = {f0, f1, f2, f3, f4};
        const int uoff[5] = {0, 3, 6, 9, 12};
        const int usz[5]  = {3, 3, 3, 3, 1};
        int u = s - 46;
        int l = (u < 3) ? 0 : (u < 6) ? 1 : (u < 9) ? 2 : (u < 12) ? 3 : 4;
        return fast_tanh(fs[l][c * usz[l] + (u - uoff[l])]);
    }
}

// -------------------------------------------------------------------------
// Generic slow logits (gated fallback only; reads the warp's shared slab).
// -------------------------------------------------------------------------
__device__ __noinline__ float logits_slow(const float* P, float t)
{
    float h[3];
#pragma unroll 1
    for (int i = 0; i < 3; i++) {
        float g = fmaf(P[i], t, P[33 + i]);
        h[i] = g + P[46 + i] * tanhf(g);
    }
#pragma unroll 1
    for (int l = 1; l < 4; l++) {
        const float* M = P + 3 + (l - 1) * 9;
        float g[3];
#pragma unroll 1
        for (int r = 0; r < 3; r++) {
            float s = P[33 + 3 * l + r];
#pragma unroll 1
            for (int k = 0; k < 3; k++) s = fmaf(M[3 * r + k], h[k], s);
            g[r] = s + P[46 + 3 * l + r] * tanhf(s);
        }
        h[0] = g[0]; h[1] = g[1]; h[2] = g[2];
    }
    float o = P[33 + 12];
#pragma unroll 1
    for (int k = 0; k < 3; k++) o = fmaf(P[30 + k], h[k], o);
    return o + P[46 + 12] * tanhf(o);
}

__device__ __forceinline__ float lk_from_LU(float L, float U)
{
    float su = L + U;
    float s = (su > 0.0f) ? -1.0f : ((su < 0.0f) ? 1.0f : 0.0f);  // -sign(L+U)
    float lk = fabsf(fast_sigmoid(s * U) - fast_sigmoid(s * L));
    return fmaxf(lk, 1e-9f);
}

// -------------------------------------------------------------------------
// Single fused kernel, v4: WARP-SHUFFLE prologue. R6 stream shape (1
// float4/thread, warp = 32 consecutive groups, 32 | 2304 -> warp is
// channel-uniform). Per warp: 2 scattered LDG/lane fetch the 59 params
// (lane i holds slots i and 32+i), then ALL lanes redundantly compose the
// affine collapse logits(t)=a*t+b via compile-time __shfl_sync broadcasts —
// no shared memory, no block barrier, no polling. The ~100-cycle chain
// hides under the warp's own input-load latency. Exact when all tanh gates
// are zero (one ballot detects); gated fallback spills to shared only when
// taken.
// -------------------------------------------------------------------------
__global__ void __launch_bounds__(256, 6) eb_fused(
    const float4* __restrict__ x4, const float4* __restrict__ n4,
    float* __restrict__ out, int n4tot,
    const float* __restrict__ m0, const float* __restrict__ m1,
    const float* __restrict__ m2, const float* __restrict__ m3,
    const float* __restrict__ m4,
    const float* __restrict__ b0, const float* __restrict__ b1,
    const float* __restrict__ b2, const float* __restrict__ b3,
    const float* __restrict__ b4,
    const float* __restrict__ f0, const float* __restrict__ f1,
    const float* __restrict__ f2, const float* __restrict__ f3,
    const float* __restrict__ f4)
{
    __shared__ float S[8][PSTRIDE];   // used only on the gated (cold) path
    int warp = threadIdx.x >> 5;
    int lane = threadIdx.x & 31;

    unsigned g = blockIdx.x * 256u + threadIdx.x;   // this thread's group
    unsigned wb = g - (unsigned)lane;               // warp's first group

    // Streaming loads first — the prologue hides under their latency.
    float4 xv = __ldcs(x4 + g);
    float4 nv = __ldcs(n4 + g);

    unsigned c = (wb / HW4) % CC;   // channel, uniform across the warp

    // Lane-parallel param fetch+transform: lane i -> slots i and 32+i.
    float r0 = load_slot(lane, c, m0, m1, m2, m3, m4,
                         b0, b1, b2, b3, b4, f0, f1, f2, f3, f4);
    float r1 = 0.0f;
    if (lane + 32 < PSTRIDE)
        r1 = load_slot(lane + 32, c, m0, m1, m2, m3, m4,
                       b0, b1, b2, b3, b4, f0, f1, f2, f3, f4);

    // Gate detection: tf slots are 46..58 -> r1 of lanes 14..26.
    bool my_tf = (lane >= 14 && lane <= 26) && (r1 != 0.0f);
    bool gated = __ballot_sync(0xffffffffu, my_tf) != 0u;

    // v = x + noise is param-independent: store it while shuffles fly.
    float4 v = make_float4(xv.x + nv.x, xv.y + nv.y, xv.z + nv.z, xv.w + nv.w);
    float4* o4 = (float4*)out;
    __stcs(o4 + g, v);  // outputs = v

    // Redundant all-lane affine composition via warp shuffles.
#define SHV(s) ((s) < 32 ? __shfl_sync(0xffffffffu, r0, (s)) \
                         : __shfl_sync(0xffffffffu, r1, (s) - 32))
    float a0 = SHV(0),  a1 = SHV(1),  a2 = SHV(2);
    float w0 = SHV(33), w1 = SHV(34), w2 = SHV(35);
#pragma unroll
    for (int l = 1; l < 4; l++) {
        float M0 = SHV(3 + (l-1)*9 + 0), M1 = SHV(3 + (l-1)*9 + 1), M2 = SHV(3 + (l-1)*9 + 2);
        float M3 = SHV(3 + (l-1)*9 + 3), M4 = SHV(3 + (l-1)*9 + 4), M5 = SHV(3 + (l-1)*9 + 5);
        float M6 = SHV(3 + (l-1)*9 + 6), M7 = SHV(3 + (l-1)*9 + 7), M8 = SHV(3 + (l-1)*9 + 8);
        float B0 = SHV(33 + 3*l + 0), B1 = SHV(33 + 3*l + 1), B2 = SHV(33 + 3*l + 2);
        float na0 = M0*a0 + M1*a1 + M2*a2;
        float na1 = M3*a0 + M4*a1 + M5*a2;
        float na2 = M6*a0 + M7*a1 + M8*a2;
        float nw0 = M0*w0 + M1*w1 + M2*w2 + B0;
        float nw1 = M3*w0 + M4*w1 + M5*w2 + B1;
        float nw2 = M6*w0 + M7*w1 + M8*w2 + B2;
        a0 = na0; a1 = na1; a2 = na2;
        w0 = nw0; w1 = nw1; w2 = nw2;
    }
    {
        float s30 = SHV(30), s31 = SHV(31), s32 = SHV(32), b12 = SHV(45);
        a0 = s30*a0 + s31*a1 + s32*a2;          // a
        w0 = s30*w0 + s31*w1 + s32*w2 + b12;    // b
    }
#undef SHV
    float a = a0;
    float bm = w0 - 0.5f * a0;

    float4 lk;
    if (!gated) {
        float Lx = fmaf(a, v.x, bm), Ly = fmaf(a, v.y, bm);
        float Lz = fmaf(a, v.z, bm), Lw = fmaf(a, v.w, bm);
        lk.x = lk_from_LU(Lx, Lx + a);
        lk.y = lk_from_LU(Ly, Ly + a);
        lk.z = lk_from_LU(Lz, Lz + a);
        lk.w = lk_from_LU(Lw, Lw + a);
    } else {
        // Cold path: spill transformed params to shared, then full MLP.
        float* W = S[warp];
        W[lane] = r0;
        if (lane + 32 < PSTRIDE) W[lane + 32] = r1;
        __syncwarp();
        lk.x = lk_from_LU(logits_slow(W, v.x - 0.5f), logits_slow(W, v.x + 0.5f));
        lk.y = lk_from_LU(logits_slow(W, v.y - 0.5f), logits_slow(W, v.y + 0.5f));
        lk.z = lk_from_LU(logits_slow(W, v.z - 0.5f), logits_slow(W, v.z + 0.5f));
        lk.w = lk_from_LU(logits_slow(W, v.w - 0.5f), logits_slow(W, v.w + 0.5f));
    }
    __stcs(o4 + n4tot + g, lk);  // likelihood
}

extern "C" void kernel_launch(void* const* d_in, const int* in_sizes, int n_in,
                              void* d_out, int out_size)
{
    const float* X  = (const float*)d_in[0];
    const float* NZ = (const float*)d_in[1];

    const float *m[5], *b[5], *f[5];
    if (in_sizes[3] == 3 * in_sizes[2]) {      // signature order
        for (int i = 0; i < 5; i++) {
            m[i] = (const float*)d_in[2 + i];
            b[i] = (const float*)d_in[7 + i];
            f[i] = (const float*)d_in[12 + i];
        }
    } else {                                   // dict order m,b,f interleaved
        for (int i = 0; i < 5; i++) {
            m[i] = (const float*)d_in[2 + 3 * i];
            b[i] = (const float*)d_in[3 + 3 * i];
            f[i] = (const float*)d_in[4 + 3 * i];
        }
    }

    int N = in_sizes[0];  // B*C*H*W = 28,311,552
    int blocks = N / 1024;  // 256 threads * 4 elems

    eb_fused<<<blocks, 256>>>(
        (const float4*)X, (const float4*)NZ, (float*)d_out, N / 4,
        m[0], m[1], m[2], m[3], m[4],
        b[0], b[1], b[2], b[3], b[4],
        f[0], f[1], f[2], f[3], f[4]);
}